// round 16
// baseline (speedup 1.0000x reference)
#include <cuda_runtime.h>
#include <cuda_fp16.h>

#define Hh 256
#define Ww 512
#define Bn 4
#define SPANK 11
#define NOFF 242
#define NPIX (Bn*Hh*Ww)
#define NWRD (NPIX/2)        // 262144 pair-words

#define RGB_S 8.493218083f
#define DEP_S 4.2466090415f

#define TBX 32
#define TBY 16
#define HYr 27
#define ROWB0 448            // 28 words * 16B (fp16 rgbz, 2 px/word)
#define PLANE0 12096
#define BASE1 24192          // after 2 plane-0 copies
#define ROWB1 224            // 28 words * 8B (fp8 y0,y1,d, 2 px/word)
#define PLANE1 6048
#define SMEMB 36288
#define SENT 0x56405640u     // half2(100.0, 100.0) sentinel

__device__ uint4  g_e0[NWRD], g_o0[NWRD];   // plane0 even/odd: {R2,G2,B2,Z2}
__device__ uint2  g_e1[NWRD], g_o1[NWRD];   // plane1 even/odd: {y0y0 y1y1 | dd --}
__device__ float  g_aF[256], g_aB[256];
__device__ double g_ce[3];
__device__ float  g_rowFull[Hh];
__device__ float  g_rowHead[Hh][12];
__device__ float  g_rowTail[Hh][12];

__device__ __forceinline__ __half2 h2ex2(__half2 x) {
    unsigned r;
    asm("ex2.approx.f16x2 %0, %1;" : "=r"(r) : "r"(*(unsigned*)&x));
    return *(__half2*)&r;
}
__device__ __forceinline__ __half2 e2h(unsigned s) {
    unsigned r;
    asm("cvt.rn.f16x2.e4m3x2 %0, %1;" : "=r"(r) : "h"((unsigned short)s));
    return *(__half2*)&r;
}
__device__ __forceinline__ unsigned h2e(float lo, float hi) {
    unsigned short r;
    asm("cvt.rn.satfinite.e4m3x2.f32 %0, %1, %2;" : "=h"(r) : "f"(hi), "f"(lo));
    return (unsigned)r;
}

__global__ void k_zero() {
    int t = threadIdx.x;
    if (t < 256) { g_aF[t] = 0.f; g_aB[t] = 0.f; }
    if (t < 3) g_ce[t] = 0.0;
}

// ---- prep: thread per even pair-word (2 pixels), writes packed planes ----
__global__ void k_prep(const float* __restrict__ logit,
                       const long long* __restrict__ target,
                       const float* __restrict__ image,
                       const float* __restrict__ depth,
                       const float* __restrict__ dstm) {
    int w = blockIdx.x * blockDim.x + threadIdx.x;
    float ce_d = 0.f, ce_a = 0.f, d_s = 0.f;
    if (w < NWRD) {
        int b = w >> 16;
        int p2 = w & 65535;
        int pix = (b << 17) + (p2 << 1);
        const float* lg = logit + (size_t)b * 393216 + (p2 << 1);
        float2 L0 = *(const float2*)(lg);
        float2 L1 = *(const float2*)(lg + 131072);
        float2 L2 = *(const float2*)(lg + 262144);
        const float* im = image + (size_t)b * 393216 + (p2 << 1);
        float2 I0 = *(const float2*)(im);
        float2 I1 = *(const float2*)(im + 131072);
        float2 I2 = *(const float2*)(im + 262144);
        float2 Dp = *(const float2*)(depth + pix);
        float2 Ds = *(const float2*)(dstm + pix);
        longlong2 T = *(const longlong2*)(target + pix);

        float y0[2], y1[2], lce[2];
        float l0a[2] = {L0.x, L0.y}, l1a[2] = {L1.x, L1.y}, l2a[2] = {L2.x, L2.y};
        long long ta[2] = {T.x, T.y};
        #pragma unroll
        for (int q = 0; q < 2; q++) {
            float m = fmaxf(l0a[q], fmaxf(l1a[q], l2a[q]));
            float e0 = __expf(l0a[q] - m), e1 = __expf(l1a[q] - m), e2 = __expf(l2a[q] - m);
            float s = e0 + e1 + e2;
            float inv = 1.f / s;
            y0[q] = e0 * inv; y1[q] = e1 * inv;
            float lt = (ta[q] == 0) ? l0a[q] : ((ta[q] == 1) ? l1a[q] : l2a[q]);
            lce[q] = m + __logf(s) - lt;
        }
        __half2 R2 = __floats2half2_rn(I0.x * RGB_S, I0.y * RGB_S);
        __half2 G2 = __floats2half2_rn(I1.x * RGB_S, I1.y * RGB_S);
        __half2 B2 = __floats2half2_rn(I2.x * RGB_S, I2.y * RGB_S);
        __half2 Z2 = __floats2half2_rn(Dp.x * DEP_S, Dp.y * DEP_S);
        uint4 e0w;
        e0w.x = *(unsigned*)&R2; e0w.y = *(unsigned*)&G2;
        e0w.z = *(unsigned*)&B2; e0w.w = *(unsigned*)&Z2;
        uint2 e1w;
        e1w.x = h2e(y0[0], y0[1]) | (h2e(y1[0], y1[1]) << 16);
        e1w.y = h2e(Ds.x, Ds.y);
        g_e0[w] = e0w; g_e1[w] = e1w;
        ce_d = lce[0] * Ds.x + lce[1] * Ds.y;
        ce_a = lce[0] + lce[1];
        d_s  = Ds.x + Ds.y;
    }
    #pragma unroll
    for (int s = 16; s; s >>= 1) {
        ce_d += __shfl_xor_sync(0xffffffffu, ce_d, s);
        ce_a += __shfl_xor_sync(0xffffffffu, ce_a, s);
        d_s  += __shfl_xor_sync(0xffffffffu, d_s,  s);
    }
    __shared__ float r0[8], r1[8], r2[8];
    int lane = threadIdx.x & 31, wq = threadIdx.x >> 5;
    if (lane == 0) { r0[wq] = ce_d; r1[wq] = ce_a; r2[wq] = d_s; }
    __syncthreads();
    if (threadIdx.x == 0) {
        float a = 0.f, bb = 0.f, c = 0.f;
        #pragma unroll
        for (int i = 0; i < 8; i++) { a += r0[i]; bb += r1[i]; c += r2[i]; }
        atomicAdd(&g_ce[0], (double)a);
        atomicAdd(&g_ce[1], (double)bb);
        atomicAdd(&g_ce[2], (double)c);
    }
}

// ---- pack: derive odd-aligned planes (sentinel at row ends) ----
__global__ void k_pack() {
    int w = blockIdx.x * blockDim.x + threadIdx.x;
    if (w >= NWRD) return;
    uint4 a0 = g_e0[w]; uint2 a1 = g_e1[w];
    uint4 n0 = make_uint4(SENT, SENT, SENT, SENT);
    uint2 n1 = make_uint2(0u, 0u);
    if ((w & 255) != 255) { n0 = g_e0[w + 1]; n1 = g_e1[w + 1]; }
    uint4 o0;
    o0.x = __byte_perm(a0.x, n0.x, 0x5432);
    o0.y = __byte_perm(a0.y, n0.y, 0x5432);
    o0.z = __byte_perm(a0.z, n0.z, 0x5432);
    o0.w = __byte_perm(a0.w, n0.w, 0x5432);
    uint2 o1;
    o1.x = __byte_perm(a1.x, n1.x, 0x6341);
    o1.y = __byte_perm(a1.y, n1.y, 0x6341);
    g_o0[w] = o0; g_o1[w] = o1;
}

__global__ void k_rows(const float* __restrict__ dstm) {
    int x = blockIdx.x;
    int tid = threadIdx.x;
    int lane = tid & 31, w = tid >> 5;
    float psum = 0.f;
    for (int b = 0; b < Bn; b++) {
        const float* row = dstm + ((size_t)b * Hh + x) * Ww;
        for (int y = tid; y < Ww; y += 128) psum += row[y];
    }
    #pragma unroll
    for (int s = 16; s; s >>= 1) psum += __shfl_xor_sync(0xffffffffu, psum, s);
    __shared__ float wsum[4];
    if (lane == 0) wsum[w] = psum;
    __syncthreads();
    if (tid == 0)
        g_rowFull[x] = wsum[0] + wsum[1] + wsum[2] + wsum[3];
    if (tid < 32 && lane <= SPANK) {
        float h = 0.f;
        for (int y = 0; y < lane; y++)
            for (int b = 0; b < Bn; b++)
                h += dstm[((size_t)b * Hh + x) * Ww + y];
        g_rowHead[x][lane] = h;
        float t = 0.f;
        for (int e = 1; e <= lane; e++)
            for (int b = 0; b < Bn; b++)
                t += dstm[((size_t)b * Hh + x) * Ww + (Ww - e)];
        g_rowTail[x][lane] = t;
    }
}

// ---- CRF: lanes=offsets, half2 pixel pairs; plane1 fp8; vector halo fill ----
__global__ __launch_bounds__(128, 5) void k_crf() {
    __shared__ __align__(16) unsigned char buf[SMEMB];
    const int b  = blockIdx.z;
    const int r0 = blockIdx.y * TBY;
    const int c0 = blockIdx.x * TBX;
    const int lane = threadIdx.x;
    const int w = threadIdx.y;
    const int tid = w * 32 + lane;

    // halo fill: pure vector copies from pre-packed gmem planes
    for (int i = tid; i < 4 * HYr * 28; i += 128) {
        int sub = i / (HYr * 28);
        int r = i - sub * (HYr * 28);
        int hy = r / 28, j = r - hy * 28;
        int gy = r0 - SPANK + hy;
        int gw = (c0 >> 1) - 6 + j;
        bool inb = ((unsigned)gy < 256u) & ((unsigned)gw < 256u);
        int gi = (((b << 8) + gy) << 8) + gw;
        if (sub < 2) {
            uint4 v = make_uint4(SENT, SENT, SENT, SENT);
            if (inb) v = (sub == 0) ? g_e0[gi] : g_o0[gi];
            *(uint4*)(buf + sub * PLANE0 + hy * ROWB0 + j * 16) = v;
        } else {
            uint2 v = make_uint2(0u, 0u);
            if (inb) v = (sub == 2) ? g_e1[gi] : g_o1[gi];
            *(uint2*)(buf + BASE1 + (sub - 2) * PLANE1 + hy * ROWB1 + j * 8) = v;
        }
    }

    // per-lane offset tables (vAdj1 = vAdj0/2 derived in loop)
    int vAdj0[8];
    __half2 cd2h[8];
    #pragma unroll
    for (int g = 0; g < 8; g++) {
        int id = g * 32 + lane;
        if (id >= NOFF) id = 12;             // dummy; results land in slots>=242, unread
        int dx = id / 22 + 1;
        int r  = id - (dx - 1) * 22;
        int dy = r - SPANK; dy += (dy >= 0);
        cd2h[g] = __float2half2_rn(-0.7213475204444817f * (float)(dx*dx + dy*dy) * (1.f/36.f));
        vAdj0[g] = (dy & 1) ? (PLANE0 - dx * ROWB0 - 8 * (dy + 1))
                            : (-dx * ROWB0 - 8 * dy);
    }

    __half2 aF2[8], aB2[8];
    float accF[8], accB[8];
    const __half2 zero2 = __float2half2_rn(0.f);
    const __half2 one2  = __float2half2_rn(1.f);
    #pragma unroll
    for (int g = 0; g < 8; g++) { aF2[g] = zero2; aB2[g] = zero2; accF[g] = 0.f; accB[g] = 0.f; }

    __syncthreads();
    const unsigned char* base = buf;

    for (int rr = 0; rr < 4; rr++) {
        int hy = SPANK + 4 * w + rr;
        int oR0 = hy * ROWB0 + 6 * 16;
        int oR1 = BASE1 + hy * ROWB1 + 6 * 8;
        for (int t = 0; t < 16; t++) {
            int o0a = oR0 + t * 16;
            int o1a = oR1 + t * 8;
            uint4 o0 = *(const uint4*)(base + o0a);
            uint2 o1 = *(const uint2*)(base + o1a);
            __half2 Ro = *(__half2*)&o0.x, Go = *(__half2*)&o0.y;
            __half2 Bo = *(__half2*)&o0.z, Zo = *(__half2*)&o0.w;
            __half2 Y0o = e2h(o1.x & 0xffff);
            __half2 Y1o = e2h(o1.x >> 16);
            __half2 Do  = e2h(o1.y & 0xffff);
            __half2 A2 = __hadd2(Y0o, Y1o);          // = 1 - y2o
            __half2 y2o = __hsub2(one2, A2);
            __half2 B2 = __hsub2(y2o, Y0o);
            __half2 C2 = __hsub2(y2o, Y1o);
            #pragma unroll
            for (int g = 0; g < 8; g++) {
                uint4 v0 = *(const uint4*)(base + (o0a + vAdj0[g]));
                uint2 v1 = *(const uint2*)(base + (o1a + (vAdj0[g] / 2)));
                __half2 dR = __hsub2(Ro, *(__half2*)&v0.x);
                __half2 dG = __hsub2(Go, *(__half2*)&v0.y);
                __half2 dB = __hsub2(Bo, *(__half2*)&v0.z);
                __half2 dZ = __hsub2(Zo, *(__half2*)&v0.w);
                __half2 a1 = __hfma2(dR, __hneg2(dR), cd2h[g]);
                a1 = __hfma2(dG, __hneg2(dG), a1);
                a1 = __hfma2(dB, __hneg2(dB), a1);
                __half2 az = __hmul2(dZ, __hneg2(dZ));
                __half2 k2 = __hadd2(h2ex2(a1), h2ex2(az));   // 0 when v is halo (sentinel)
                __half2 ct = __hfma2(B2, e2h(v1.x & 0xffff), A2);
                ct = __hfma2(C2, e2h(v1.x >> 16), ct);
                __half2 kc = __hmul2(k2, ct);
                aF2[g] = __hfma2(kc, e2h(v1.y & 0xffff), aF2[g]);
                aB2[g] = __hfma2(kc, Do, aB2[g]);
            }
            if (t == 15) {                            // dump once per rr
                #pragma unroll
                for (int g = 0; g < 8; g++) {
                    float2 f = __half22float2(aF2[g]);
                    float2 bb = __half22float2(aB2[g]);
                    accF[g] += f.x + f.y;
                    accB[g] += bb.x + bb.y;
                    aF2[g] = zero2; aB2[g] = zero2;
                }
            }
        }
    }

    __syncthreads();
    float* red = (float*)buf;                  // [256][4 warps][2]
    #pragma unroll
    for (int g = 0; g < 8; g++) {
        int id = g * 32 + lane;                // dummies land in 242..255, unread
        red[(id * 4 + w) * 2 + 0] = accF[g];
        red[(id * 4 + w) * 2 + 1] = accB[g];
    }
    __syncthreads();
    for (int o = tid; o < NOFF; o += 128) {
        float f  = red[o * 8 + 0] + red[o * 8 + 2] + red[o * 8 + 4] + red[o * 8 + 6];
        float bb = red[o * 8 + 1] + red[o * 8 + 3] + red[o * 8 + 5] + red[o * 8 + 7];
        atomicAdd(&g_aF[o], f);
        atomicAdd(&g_aB[o], bb);
    }
}

__global__ void k_final(float* __restrict__ out) {
    __shared__ float  sR[23][Hh];
    __shared__ double sFull[23], sHead[23][12], sTail[23][12];
    __shared__ double rect[23 * 23];
    __shared__ double red[256];
    int tid = threadIdx.x;
    int lane = tid & 31, w8 = tid >> 5;
    {
        int x = tid;
        float full = g_rowFull[x];
        float head[12], tail[12];
        #pragma unroll
        for (int i = 0; i < 12; i++) { head[i] = g_rowHead[x][i]; tail[i] = g_rowTail[x][i]; }
        #pragma unroll
        for (int yi = 0; yi < 23; yi++) {
            int dy = yi - SPANK;
            int c = dy < 0 ? -dy : 0;
            int e = dy > 0 ? dy : 0;
            sR[yi][x] = full - head[c] - tail[e];
        }
    }
    __syncthreads();
    for (int yi = w8; yi < 23; yi += 8) {
        float p = 0.f;
        for (int x = lane; x < Hh; x += 32) p += sR[yi][x];
        #pragma unroll
        for (int s = 16; s; s >>= 1) p += __shfl_xor_sync(0xffffffffu, p, s);
        if (lane == 0) sFull[yi] = (double)p;
        if (lane <= SPANK) {
            float h = 0.f;
            for (int x = 0; x < lane; x++) h += sR[yi][x];
            sHead[yi][lane] = (double)h;
            float t = 0.f;
            for (int e = 1; e <= lane; e++) t += sR[yi][Hh - e];
            sTail[yi][lane] = (double)t;
        }
    }
    __syncthreads();
    for (int t = tid; t < 23 * 23; t += 256) {
        int xi = t / 23, yi = t - xi * 23;
        int dx = xi - SPANK;
        int a = dx < 0 ? -dx : 0;
        int bb = dx > 0 ? dx : 0;
        rect[t] = sFull[yi] - sHead[yi][a] - sTail[yi][bb];
    }
    __syncthreads();
    double e = 0.0;
    if (tid < NOFF) {
        int dx = tid / 22 + 1;
        int r = tid - (dx - 1) * 22;
        int dy = r - SPANK;
        dy += (dy >= 0);
        double denF = rect[(SPANK - dx) * 23 + (SPANK - dy)];
        double denB = rect[(SPANK + dx) * 23 + (SPANK + dy)];
        e = (double)g_aF[tid] / denF + (double)g_aB[tid] / denB;
    }
    red[tid] = e;
    __syncthreads();
    for (int s = 128; s; s >>= 1) {
        if (tid < s) red[tid] += red[tid + s];
        __syncthreads();
    }
    if (tid == 0) {
        out[1] = (float)(red[0] / 529.0);
        double N = (double)NPIX;
        double SA = g_ce[0], SB = g_ce[1], SC = g_ce[2];
        double lo1 = SA / N;
        double lo2 = (SB - SA) / N;
        double cnt = SC / N;
        out[0] = (float)(lo1 * (1.0 - cnt) + lo2 * cnt);
    }
}

extern "C" void kernel_launch(void* const* d_in, const int* in_sizes, int n_in,
                              void* d_out, int out_size) {
    (void)in_sizes; (void)n_in; (void)out_size;
    const float*     logit  = (const float*)d_in[0];
    const long long* target = (const long long*)d_in[1];
    const float*     image  = (const float*)d_in[2];
    const float*     depth  = (const float*)d_in[3];
    const float*     dstm   = (const float*)d_in[4];
    float* out = (float*)d_out;

    k_zero<<<1, 256>>>();
    k_prep<<<NWRD / 256, 256>>>(logit, target, image, depth, dstm);
    k_pack<<<NWRD / 256, 256>>>();
    k_rows<<<Hh, 128>>>(dstm);
    dim3 blk(32, 4);
    dim3 grd(Ww / TBX, Hh / TBY, Bn);
    k_crf<<<grd, blk>>>();
    k_final<<<1, 256>>>(out);
}

// round 17
// speedup vs baseline: 1.5902x; 1.5902x over previous
#include <cuda_runtime.h>
#include <cuda_fp16.h>

#define Hh 256
#define Ww 512
#define Bn 4
#define SPANK 11
#define NOFF 242
#define NPIX (Bn*Hh*Ww)

#define RGB_S 8.493218083f
#define DEP_S 4.2466090415f

#define TBX 32
#define TBY 16
#define HYr 27
#define NHX 57
#define ROWB0 448            // 28 words * 16B (fp16 rgbz, 2 px/word)
#define PLANE0 12096
#define BASE1 24192          // after 2 plane-0 copies
#define ROWB1 224            // 28 words * 8B (fp8 y0,y1,d, 2 px/word)
#define PLANE1 6048
#define SMEMB 36288

__device__ uint4  g_PK[NPIX];   // {r,g | b,z | fp8 y0|y1|d | unused}
__device__ float  g_aF[256], g_aB[256];
__device__ double g_ce[3];
__device__ float  g_rowFull[Hh];
__device__ float  g_rowHead[Hh][12];
__device__ float  g_rowTail[Hh][12];

__device__ __forceinline__ __half2 h2ex2(__half2 x) {
    unsigned r;
    asm("ex2.approx.f16x2 %0, %1;" : "=r"(r) : "r"(*(unsigned*)&x));
    return *(__half2*)&r;
}
__device__ __forceinline__ __half2 e2h(unsigned s) {
    unsigned r;
    asm("cvt.rn.f16x2.e4m3x2 %0, %1;" : "=r"(r) : "h"((unsigned short)s));
    return *(__half2*)&r;
}
__device__ __forceinline__ unsigned short h2e(float lo, float hi) {
    unsigned short r;
    asm("cvt.rn.satfinite.e4m3x2.f32 %0, %1, %2;" : "=h"(r) : "f"(hi), "f"(lo));
    return r;
}

__global__ void k_zero() {
    int t = threadIdx.x;
    if (t < 256) { g_aF[t] = 0.f; g_aB[t] = 0.f; }
    if (t < 3) g_ce[t] = 0.0;
}

__global__ void k_prep(const float* __restrict__ logit,
                       const long long* __restrict__ target,
                       const float* __restrict__ image,
                       const float* __restrict__ depth,
                       const float* __restrict__ dstm) {
    int idx = blockIdx.x * blockDim.x + threadIdx.x;
    float ce_d = 0.f, ce_a = 0.f, d_s = 0.f;
    if (idx < NPIX) {
        int b = idx / (Hh * Ww);
        int p = idx - b * (Hh * Ww);
        const float* lg = logit + (size_t)b * 3 * Hh * Ww + p;
        float l0 = lg[0], l1 = lg[Hh * Ww], l2 = lg[2 * Hh * Ww];
        float m = fmaxf(l0, fmaxf(l1, l2));
        float e0 = __expf(l0 - m), e1 = __expf(l1 - m), e2 = __expf(l2 - m);
        float s = e0 + e1 + e2;
        float inv = 1.f / s;
        const float* im = image + (size_t)b * 3 * Hh * Ww + p;
        float dv = dstm[idx];
        __half2 h0 = __floats2half2_rn(im[0] * RGB_S, im[Hh * Ww] * RGB_S);
        __half2 h1 = __floats2half2_rn(im[2 * Hh * Ww] * RGB_S, depth[idx] * DEP_S);
        unsigned short yy = h2e(e0 * inv, e1 * inv);   // bytes: y0 | y1<<8
        unsigned short dd = h2e(dv, 0.f);              // byte:  d
        uint4 pk;
        pk.x = *(unsigned*)&h0; pk.y = *(unsigned*)&h1;
        pk.z = (unsigned)yy | ((unsigned)dd << 16);
        pk.w = 0u;
        g_PK[idx] = pk;
        long long t = target[idx];
        float lt = (t == 0) ? l0 : ((t == 1) ? l1 : l2);
        float lce = m + __logf(s) - lt;
        ce_d = lce * dv; ce_a = lce; d_s = dv;
    }
    #pragma unroll
    for (int s = 16; s; s >>= 1) {
        ce_d += __shfl_xor_sync(0xffffffffu, ce_d, s);
        ce_a += __shfl_xor_sync(0xffffffffu, ce_a, s);
        d_s  += __shfl_xor_sync(0xffffffffu, d_s,  s);
    }
    __shared__ float r0[8], r1[8], r2[8];
    int lane = threadIdx.x & 31, w = threadIdx.x >> 5;
    if (lane == 0) { r0[w] = ce_d; r1[w] = ce_a; r2[w] = d_s; }
    __syncthreads();
    if (threadIdx.x == 0) {
        float a = 0.f, bb = 0.f, c = 0.f;
        #pragma unroll
        for (int i = 0; i < 8; i++) { a += r0[i]; bb += r1[i]; c += r2[i]; }
        atomicAdd(&g_ce[0], (double)a);
        atomicAdd(&g_ce[1], (double)bb);
        atomicAdd(&g_ce[2], (double)c);
    }
}

// ---- rows: full-row sums + parallel head/tail prefix scans ----
__global__ void k_rows(const float* __restrict__ dstm) {
    int x = blockIdx.x;
    int tid = threadIdx.x;
    int lane = tid & 31, w = tid >> 5;
    float psum = 0.f;
    for (int b = 0; b < Bn; b++) {
        const float* row = dstm + ((size_t)b * Hh + x) * Ww;
        for (int y = tid; y < Ww; y += 128) psum += row[y];
    }
    #pragma unroll
    for (int s = 16; s; s >>= 1) psum += __shfl_xor_sync(0xffffffffu, psum, s);
    __shared__ float wsum[4];
    if (lane == 0) wsum[w] = psum;

    if (w == 1) {                       // heads via warp scan (lanes 0..10)
        float v = 0.f;
        if (lane < SPANK) {
            #pragma unroll
            for (int b = 0; b < Bn; b++)
                v += dstm[((size_t)b * Hh + x) * Ww + lane];
        }
        #pragma unroll
        for (int d = 1; d < 16; d <<= 1) {
            float t = __shfl_up_sync(0xffffffffu, v, d);
            if (lane >= d) v += t;
        }
        if (lane < SPANK) g_rowHead[x][lane + 1] = v;
        if (lane == 0)    g_rowHead[x][0] = 0.f;
    }
    if (w == 2) {                       // tails via warp scan (lanes 0..10)
        float v = 0.f;
        if (lane < SPANK) {
            #pragma unroll
            for (int b = 0; b < Bn; b++)
                v += dstm[((size_t)b * Hh + x) * Ww + (Ww - 1 - lane)];
        }
        #pragma unroll
        for (int d = 1; d < 16; d <<= 1) {
            float t = __shfl_up_sync(0xffffffffu, v, d);
            if (lane >= d) v += t;
        }
        if (lane < SPANK) g_rowTail[x][lane + 1] = v;
        if (lane == 0)    g_rowTail[x][0] = 0.f;
    }
    __syncthreads();
    if (tid == 0)
        g_rowFull[x] = wsum[0] + wsum[1] + wsum[2] + wsum[3];
}

// ---- CRF: lanes=offsets, half2 pixel pairs; plane1 fp8; 5 CTAs/SM ----
__global__ __launch_bounds__(128, 5) void k_crf() {
    __shared__ __align__(16) unsigned char buf[SMEMB];
    const int b  = blockIdx.z;
    const int r0 = blockIdx.y * TBY;
    const int c0 = blockIdx.x * TBX;
    const int lane = threadIdx.x;
    const int w = threadIdx.y;
    const int tid = w * 32 + lane;

    unsigned short* H = (unsigned short*)buf;
    for (int i = tid; i < HYr * NHX; i += 128) {
        int hy = i / NHX, hx = i - hy * NHX;
        int gy = r0 - SPANK + hy;
        int gx = c0 - 12 + hx;
        unsigned rg = 0x56405640u, bz = 0x56405640u, yd = 0u;   // sentinel 100.0
        if (gy >= 0 && gy < Hh && gx >= 0 && gx < Ww) {
            uint4 pk = g_PK[(b * Hh + gy) * Ww + gx];
            rg = pk.x; bz = pk.y; yd = pk.z;
        }
        unsigned char y0b = yd & 0xff, y1b = (yd >> 8) & 0xff, db = (yd >> 16) & 0xff;
        if (hx < 56) {
            int s = hx & 1;
            int be = (hy * 28 + (hx >> 1)) * 8 + s;
            H[be + 0] = (unsigned short)rg;  H[be + 2] = (unsigned short)(rg >> 16);
            H[be + 4] = (unsigned short)bz;  H[be + 6] = (unsigned short)(bz >> 16);
            int b1 = BASE1 + (hy * 28 + (hx >> 1)) * 8 + s;
            buf[b1 + 0] = y0b; buf[b1 + 2] = y1b; buf[b1 + 4] = db;
        }
        if (hx >= 1) {
            int ho = hx - 1;
            int s = ho & 1;
            int bo = (PLANE0 / 2) + (hy * 28 + (ho >> 1)) * 8 + s;
            H[bo + 0] = (unsigned short)rg;  H[bo + 2] = (unsigned short)(rg >> 16);
            H[bo + 4] = (unsigned short)bz;  H[bo + 6] = (unsigned short)(bz >> 16);
            int b1 = BASE1 + PLANE1 + (hy * 28 + (ho >> 1)) * 8 + s;
            buf[b1 + 0] = y0b; buf[b1 + 2] = y1b; buf[b1 + 4] = db;
        }
    }

    // per-lane offset tables (vAdj1 = vAdj0>>1 derived in loop: exact, even values)
    int vAdj0[8];
    __half2 cd2h[8];
    #pragma unroll
    for (int g = 0; g < 8; g++) {
        int id = g * 32 + lane;
        if (id >= NOFF) id = 12;             // dummy; results land in slots>=242, unread
        int dx = id / 22 + 1;
        int r  = id - (dx - 1) * 22;
        int dy = r - SPANK; dy += (dy >= 0);
        cd2h[g] = __float2half2_rn(-0.7213475204444817f * (float)(dx*dx + dy*dy) * (1.f/36.f));
        vAdj0[g] = (dy & 1) ? (PLANE0 - dx * ROWB0 - 8 * (dy + 1))
                            : (-dx * ROWB0 - 8 * dy);
    }

    __half2 aF2[8], aB2[8];
    float accF[8], accB[8];
    const __half2 zero2 = __float2half2_rn(0.f);
    const __half2 one2  = __float2half2_rn(1.f);
    #pragma unroll
    for (int g = 0; g < 8; g++) { aF2[g] = zero2; aB2[g] = zero2; accF[g] = 0.f; accB[g] = 0.f; }

    __syncthreads();
    const unsigned char* base = buf;

    for (int rr = 0; rr < 4; rr++) {
        int hy = SPANK + 4 * w + rr;
        int oR0 = hy * ROWB0 + 6 * 16;
        int oR1 = BASE1 + hy * ROWB1 + 6 * 8;
        for (int t = 0; t < 16; t++) {
            int o0a = oR0 + t * 16;
            int o1a = oR1 + t * 8;
            uint4 o0 = *(const uint4*)(base + o0a);
            uint2 o1 = *(const uint2*)(base + o1a);
            __half2 Ro = *(__half2*)&o0.x, Go = *(__half2*)&o0.y;
            __half2 Bo = *(__half2*)&o0.z, Zo = *(__half2*)&o0.w;
            __half2 Y0o = e2h(o1.x & 0xffff);
            __half2 Y1o = e2h(o1.x >> 16);
            __half2 Do  = e2h(o1.y & 0xffff);
            __half2 A2 = __hadd2(Y0o, Y1o);          // = 1 - y2o
            __half2 y2o = __hsub2(one2, A2);
            __half2 B2 = __hsub2(y2o, Y0o);
            __half2 C2 = __hsub2(y2o, Y1o);
            #pragma unroll
            for (int g = 0; g < 8; g++) {
                uint4 v0 = *(const uint4*)(base + (o0a + vAdj0[g]));
                uint2 v1 = *(const uint2*)(base + (o1a + (vAdj0[g] >> 1)));
                __half2 dR = __hsub2(Ro, *(__half2*)&v0.x);
                __half2 dG = __hsub2(Go, *(__half2*)&v0.y);
                __half2 dB = __hsub2(Bo, *(__half2*)&v0.z);
                __half2 dZ = __hsub2(Zo, *(__half2*)&v0.w);
                __half2 a1 = __hfma2(dR, __hneg2(dR), cd2h[g]);
                a1 = __hfma2(dG, __hneg2(dG), a1);
                a1 = __hfma2(dB, __hneg2(dB), a1);
                __half2 az = __hmul2(dZ, __hneg2(dZ));
                __half2 k2 = __hadd2(h2ex2(a1), h2ex2(az));   // 0 when v is halo (sentinel)
                __half2 ct = __hfma2(B2, e2h(v1.x & 0xffff), A2);
                ct = __hfma2(C2, e2h(v1.x >> 16), ct);
                __half2 kc = __hmul2(k2, ct);
                aF2[g] = __hfma2(kc, e2h(v1.y & 0xffff), aF2[g]);
                aB2[g] = __hfma2(kc, Do, aB2[g]);
            }
            if (t == 15) {                            // dump once per rr
                #pragma unroll
                for (int g = 0; g < 8; g++) {
                    float2 f = __half22float2(aF2[g]);
                    float2 bb = __half22float2(aB2[g]);
                    accF[g] += f.x + f.y;
                    accB[g] += bb.x + bb.y;
                    aF2[g] = zero2; aB2[g] = zero2;
                }
            }
        }
    }

    __syncthreads();
    float* red = (float*)buf;                  // [256][4 warps][2]
    #pragma unroll
    for (int g = 0; g < 8; g++) {
        int id = g * 32 + lane;                // dummies land in 242..255, unread
        red[(id * 4 + w) * 2 + 0] = accF[g];
        red[(id * 4 + w) * 2 + 1] = accB[g];
    }
    __syncthreads();
    for (int o = tid; o < NOFF; o += 128) {
        float f  = red[o * 8 + 0] + red[o * 8 + 2] + red[o * 8 + 4] + red[o * 8 + 6];
        float bb = red[o * 8 + 1] + red[o * 8 + 3] + red[o * 8 + 5] + red[o * 8 + 7];
        atomicAdd(&g_aF[o], f);
        atomicAdd(&g_aB[o], bb);
    }
}

__global__ void k_final(float* __restrict__ out) {
    __shared__ float  sR[23][Hh];
    __shared__ double sFull[23], sHead[23][12], sTail[23][12];
    __shared__ double rect[23 * 23];
    __shared__ double wred[8];
    int tid = threadIdx.x;
    int lane = tid & 31, w8 = tid >> 5;
    {
        int x = tid;
        float full = g_rowFull[x];
        float head[12], tail[12];
        #pragma unroll
        for (int i = 0; i < 12; i++) { head[i] = g_rowHead[x][i]; tail[i] = g_rowTail[x][i]; }
        #pragma unroll
        for (int yi = 0; yi < 23; yi++) {
            int dy = yi - SPANK;
            int c = dy < 0 ? -dy : 0;
            int e = dy > 0 ? dy : 0;
            sR[yi][x] = full - head[c] - tail[e];
        }
    }
    __syncthreads();
    for (int yi = w8; yi < 23; yi += 8) {
        float p = 0.f;
        for (int x = lane; x < Hh; x += 32) p += sR[yi][x];
        #pragma unroll
        for (int s = 16; s; s >>= 1) p += __shfl_xor_sync(0xffffffffu, p, s);
        if (lane == 0) sFull[yi] = (double)p;
        if (lane <= SPANK) {
            float h = 0.f;
            for (int x = 0; x < lane; x++) h += sR[yi][x];
            sHead[yi][lane] = (double)h;
            float t = 0.f;
            for (int e = 1; e <= lane; e++) t += sR[yi][Hh - e];
            sTail[yi][lane] = (double)t;
        }
    }
    __syncthreads();
    for (int t = tid; t < 23 * 23; t += 256) {
        int xi = t / 23, yi = t - xi * 23;
        int dx = xi - SPANK;
        int a = dx < 0 ? -dx : 0;
        int bb = dx > 0 ? dx : 0;
        rect[t] = sFull[yi] - sHead[yi][a] - sTail[yi][bb];
    }
    __syncthreads();
    double e = 0.0;
    if (tid < NOFF) {
        int dx = tid / 22 + 1;
        int r = tid - (dx - 1) * 22;
        int dy = r - SPANK;
        dy += (dy >= 0);
        double denF = rect[(SPANK - dx) * 23 + (SPANK - dy)];
        double denB = rect[(SPANK + dx) * 23 + (SPANK + dy)];
        e = (double)g_aF[tid] / denF + (double)g_aB[tid] / denB;
    }
    #pragma unroll
    for (int s = 16; s; s >>= 1) e += __shfl_xor_sync(0xffffffffu, e, s);
    if (lane == 0) wred[w8] = e;
    __syncthreads();
    if (tid == 0) {
        double tot = 0.0;
        #pragma unroll
        for (int i = 0; i < 8; i++) tot += wred[i];
        out[1] = (float)(tot / 529.0);
        double N = (double)NPIX;
        double SA = g_ce[0], SB = g_ce[1], SC = g_ce[2];
        double lo1 = SA / N;
        double lo2 = (SB - SA) / N;
        double cnt = SC / N;
        out[0] = (float)(lo1 * (1.0 - cnt) + lo2 * cnt);
    }
}

extern "C" void kernel_launch(void* const* d_in, const int* in_sizes, int n_in,
                              void* d_out, int out_size) {
    (void)in_sizes; (void)n_in; (void)out_size;
    const float*     logit  = (const float*)d_in[0];
    const long long* target = (const long long*)d_in[1];
    const float*     image  = (const float*)d_in[2];
    const float*     depth  = (const float*)d_in[3];
    const float*     dstm   = (const float*)d_in[4];
    float* out = (float*)d_out;

    k_zero<<<1, 256>>>();
    k_prep<<<NPIX / 256, 256>>>(logit, target, image, depth, dstm);
    k_rows<<<Hh, 128>>>(dstm);
    dim3 blk(32, 4);
    dim3 grd(Ww / TBX, Hh / TBY, Bn);
    k_crf<<<grd, blk>>>();
    k_final<<<1, 256>>>(out);
}